// round 9
// baseline (speedup 1.0000x reference)
#include <cuda_runtime.h>
#include <cstdint>

#define N_MAX 50000
#define E_MAX 800000
#define IN_DIM 128
#define HEADS 4
#define OUT_DIM 32
#define OC (HEADS*OUT_DIM)   // 128
#define NEG_SLOPE 0.2f
#define EPS_F 1e-16f

// ---------------- scratch (no allocations allowed; 16B-aligned) ----------------
__device__ __align__(16) float g_h[N_MAX * OC];          // 25.6 MB
__device__ __align__(16) float g_asrc[N_MAX * HEADS];
__device__ __align__(16) float g_adst[N_MAX * HEADS];
__device__ __align__(16) float g_sinv[N_MAX * HEADS];    // 1/(sum+eps)
__device__ __align__(16) float g_wa[8 * IN_DIM];         // W^T * {att_src(4), att_dst(4)}
__device__ __align__(16) int   g_deg[N_MAX];
__device__ __align__(16) int   g_cur[N_MAX];
__device__ __align__(16) int   g_off[N_MAX + 1];
__device__ __align__(16) int   g_csr_src[E_MAX];
__device__ int g_idx64;   // 1 if edge_index is int64, 0 if int32

// ---------------- helpers ----------------
__device__ __forceinline__ float lrelu(float a) {
    return a > 0.f ? a : NEG_SLOPE * a;
}
__device__ __forceinline__ int2 load_edge(const void* ei, int e, int eidx) {
    if (g_idx64) {
        const long long* p = (const long long*)ei;
        return make_int2((int)p[eidx], (int)p[e + eidx]);
    } else {
        const int* p = (const int*)ei;
        return make_int2(p[eidx], p[e + eidx]);
    }
}

// ---------------- K detect: edge_index dtype ----------------
__global__ void k_detect(const unsigned* __restrict__ raw) {
    unsigned any = 0;
    for (int i = threadIdx.x; i < 128; i += 32) any |= raw[2 * i + 1];
#pragma unroll
    for (int o = 16; o > 0; o >>= 1) any |= __shfl_down_sync(0xffffffffu, any, o);
    if (threadIdx.x == 0) g_idx64 = (any == 0u) ? 1 : 0;
}

// ---------------- K zero: counters ----------------
__global__ void k_zero(int n) {
    int idx = blockIdx.x * blockDim.x + threadIdx.x;
    if (idx < n) { g_deg[idx] = 0; g_cur[idx] = 0; }
}

// ---------------- K watt: wa[j][k] = sum_d att[j%4][d] * W[( (j%4)*32+d )*128 + k] ----------------
__global__ void k_watt(const float* __restrict__ W, const float* __restrict__ att_src,
                       const float* __restrict__ att_dst) {
    int idx = threadIdx.x + blockIdx.x * blockDim.x;   // 1024 threads
    if (idx >= 8 * IN_DIM) return;
    int j = idx >> 7;          // 0..7
    int k = idx & 127;
    int hd = j & 3;
    const float* att = (j >= 4) ? att_dst : att_src;
    float s = 0.f;
#pragma unroll 8
    for (int d = 0; d < OUT_DIM; d++)
        s = fmaf(att[hd * OUT_DIM + d], W[(hd * OUT_DIM + d) * IN_DIM + k], s);
    g_wa[j * IN_DIM + k] = s;
}

// ---------------- K1: h = x @ W^T + attention projections from xs tile ----------------
#define TM 64
#define WS_S 132
#define XS_S 68
__global__ void k_gemm(const float* __restrict__ x, const float* __restrict__ W, int n) {
    extern __shared__ float sm[];
    float* ws = sm;                 // 128*132
    float* xs = sm + IN_DIM * WS_S; // 128*68
    int tid = threadIdx.x;
    int tx = tid & 15, ty = tid >> 4;
    int row0 = blockIdx.x * TM;

    for (int idx = tid; idx < OC * IN_DIM; idx += 256) {
        int c = idx >> 7, k = idx & 127;
        ws[k * WS_S + c] = W[idx];
    }
    for (int idx = tid; idx < TM * IN_DIM; idx += 256) {
        int r = idx >> 7, k = idx & 127;
        int row = row0 + r;
        xs[k * XS_S + r] = (row < n) ? x[row * IN_DIM + k] : 0.f;
    }
    __syncthreads();

    float acc[4][8];
#pragma unroll
    for (int i = 0; i < 4; i++)
#pragma unroll
        for (int j = 0; j < 8; j++) acc[i][j] = 0.f;

#pragma unroll 8
    for (int k = 0; k < IN_DIM; k++) {
        float4 a  = *(const float4*)&xs[k * XS_S + ty * 4];
        float4 b0 = *(const float4*)&ws[k * WS_S + tx * 8];
        float4 b1 = *(const float4*)&ws[k * WS_S + tx * 8 + 4];
        float av[4] = {a.x, a.y, a.z, a.w};
        float bv[8] = {b0.x, b0.y, b0.z, b0.w, b1.x, b1.y, b1.z, b1.w};
#pragma unroll
        for (int i = 0; i < 4; i++)
#pragma unroll
            for (int j = 0; j < 8; j++) acc[i][j] = fmaf(av[i], bv[j], acc[i][j]);
    }

#pragma unroll
    for (int i = 0; i < 4; i++) {
        int row = row0 + ty * 4 + i;
        if (row < n) {
            *(float4*)&g_h[row * OC + tx * 8]     = make_float4(acc[i][0], acc[i][1], acc[i][2], acc[i][3]);
            *(float4*)&g_h[row * OC + tx * 8 + 4] = make_float4(acc[i][4], acc[i][5], acc[i][6], acc[i][7]);
        }
    }

    // ---- attention-projection epilogue: a = xs · wa  (xs still live in smem) ----
    __syncthreads();
    float* was = sm;   // reuse ws region: 8*128 floats
    for (int idx = tid; idx < 8 * IN_DIM; idx += 256) was[idx] = g_wa[idx];
    __syncthreads();

    int r = tid >> 2, hp = tid & 3;      // 64 rows x 4 heads
    int row = row0 + r;
    float s_ = 0.f, d_ = 0.f;
#pragma unroll 8
    for (int k = 0; k < IN_DIM; k++) {
        float xv = xs[k * XS_S + r];
        s_ = fmaf(xv, was[hp * IN_DIM + k], s_);
        d_ = fmaf(xv, was[(hp + 4) * IN_DIM + k], d_);
    }
    if (row < n) {
        g_asrc[row * HEADS + hp] = s_;
        g_adst[row * HEADS + hp] = d_;
    }
}

// ---------------- CSR build ----------------
__global__ void k_count(const void* __restrict__ ei, int e) {
    int eidx = blockIdx.x * blockDim.x + threadIdx.x;
    if (eidx >= e) return;
    int dst = (g_idx64) ? (int)((const long long*)ei)[e + eidx]
                        : ((const int*)ei)[e + eidx];
    atomicAdd(&g_deg[dst], 1);
}

__global__ void k_scan(int n) {   // single block, 1024 threads; exclusive scan of g_deg -> g_off
    __shared__ int warpsum[32];
    int tid = threadIdx.x;
    int chunk = (n + 1023) / 1024;
    int beg = tid * chunk;
    int end = min(beg + chunk, n);
    int s = 0;
    for (int i = beg; i < end; i++) s += g_deg[i];
    int lane = tid & 31, wid = tid >> 5;
    int v = s;
#pragma unroll
    for (int o = 1; o < 32; o <<= 1) {
        int t = __shfl_up_sync(0xffffffffu, v, o);
        if (lane >= o) v += t;
    }
    if (lane == 31) warpsum[wid] = v;
    __syncthreads();
    if (wid == 0) {
        int w = warpsum[lane];
#pragma unroll
        for (int o = 1; o < 32; o <<= 1) {
            int t = __shfl_up_sync(0xffffffffu, w, o);
            if (lane >= o) w += t;
        }
        warpsum[lane] = w;
    }
    __syncthreads();
    int base = ((wid > 0) ? warpsum[wid - 1] : 0) + (v - s);
    int run = base;
    for (int i = beg; i < end; i++) { g_off[i] = run; run += g_deg[i]; }
    if (tid == 0) g_off[n] = warpsum[31];
}

__global__ void k_fill(const void* __restrict__ ei, int e) {
    int eidx = blockIdx.x * blockDim.x + threadIdx.x;
    if (eidx >= e) return;
    int2 sd = load_edge(ei, e, eidx);
    int pos = g_off[sd.y] + atomicAdd(&g_cur[sd.y], 1);
    g_csr_src[pos] = sd.x;
}

// ---------------- K agg: one warp per dst node, register accumulation, no atomics ----------------
__global__ void k_agg(const float* __restrict__ bias, float* __restrict__ out, int n) {
    int w = blockIdx.x * (blockDim.x >> 5) + (threadIdx.x >> 5);
    if (w >= n) return;
    int lane = threadIdx.x & 31;
    int hd = lane >> 3;

    int off = g_off[w];
    int deg = g_off[w + 1] - off;

    float ad = g_adst[w * HEADS + hd];
    float4 acc = make_float4(0.f, 0.f, 0.f, 0.f);
    float ssum = 0.f;

    int i = 0;
    for (; i + 3 < deg; i += 4) {
        int s0 = g_csr_src[off + i];
        int s1 = g_csr_src[off + i + 1];
        int s2 = g_csr_src[off + i + 2];
        int s3 = g_csr_src[off + i + 3];
        float ex0 = __expf(lrelu(g_asrc[s0 * HEADS + hd] + ad));
        float ex1 = __expf(lrelu(g_asrc[s1 * HEADS + hd] + ad));
        float ex2 = __expf(lrelu(g_asrc[s2 * HEADS + hd] + ad));
        float ex3 = __expf(lrelu(g_asrc[s3 * HEADS + hd] + ad));
        float4 v0 = *(const float4*)&g_h[s0 * OC + lane * 4];
        float4 v1 = *(const float4*)&g_h[s1 * OC + lane * 4];
        float4 v2 = *(const float4*)&g_h[s2 * OC + lane * 4];
        float4 v3 = *(const float4*)&g_h[s3 * OC + lane * 4];
        ssum += (ex0 + ex1) + (ex2 + ex3);
        acc.x = fmaf(ex0, v0.x, fmaf(ex1, v1.x, fmaf(ex2, v2.x, fmaf(ex3, v3.x, acc.x))));
        acc.y = fmaf(ex0, v0.y, fmaf(ex1, v1.y, fmaf(ex2, v2.y, fmaf(ex3, v3.y, acc.y))));
        acc.z = fmaf(ex0, v0.z, fmaf(ex1, v1.z, fmaf(ex2, v2.z, fmaf(ex3, v3.z, acc.z))));
        acc.w = fmaf(ex0, v0.w, fmaf(ex1, v1.w, fmaf(ex2, v2.w, fmaf(ex3, v3.w, acc.w))));
    }
    for (; i < deg; i++) {
        int s0 = g_csr_src[off + i];
        float ex0 = __expf(lrelu(g_asrc[s0 * HEADS + hd] + ad));
        float4 v0 = *(const float4*)&g_h[s0 * OC + lane * 4];
        ssum += ex0;
        acc.x = fmaf(ex0, v0.x, acc.x);
        acc.y = fmaf(ex0, v0.y, acc.y);
        acc.z = fmaf(ex0, v0.z, acc.z);
        acc.w = fmaf(ex0, v0.w, acc.w);
    }

    float inv = 1.f / (ssum + EPS_F);
    float4 b = *(const float4*)&bias[lane * 4];
    acc.x = fmaf(acc.x, inv, b.x);
    acc.y = fmaf(acc.y, inv, b.y);
    acc.z = fmaf(acc.z, inv, b.z);
    acc.w = fmaf(acc.w, inv, b.w);
    *(float4*)&out[w * OC + lane * 4] = acc;

    if ((lane & 7) == 0) g_sinv[w * HEADS + hd] = inv;
}

// ---------------- K pooled: one thread per edge (multiply by precomputed 1/s) ----------------
__global__ void k_pooled(const void* __restrict__ ei, float* __restrict__ pooled, int e) {
    int eidx = blockIdx.x * blockDim.x + threadIdx.x;
    if (eidx >= e) return;
    int2 sd = load_edge(ei, e, eidx);
    float4 as = *(const float4*)&g_asrc[sd.x * HEADS];
    float4 ad = *(const float4*)&g_adst[sd.y * HEADS];
    float4 sv = *(const float4*)&g_sinv[sd.y * HEADS];
    float p = __expf(lrelu(as.x + ad.x)) * sv.x
            + __expf(lrelu(as.y + ad.y)) * sv.y
            + __expf(lrelu(as.z + ad.z)) * sv.z
            + __expf(lrelu(as.w + ad.w)) * sv.w;
    pooled[eidx] = p * 0.25f;
}

// ---------------- launch ----------------
extern "C" void kernel_launch(void* const* d_in, const int* in_sizes, int n_in,
                              void* d_out, int out_size) {
    const float* x       = (const float*)d_in[0];
    const void*  ei      = d_in[1];
    const float* W       = (const float*)d_in[2];
    const float* att_src = (const float*)d_in[3];
    const float* att_dst = (const float*)d_in[4];
    const float* bias    = (const float*)d_in[5];

    int n = in_sizes[0] / IN_DIM;
    int e = in_sizes[1] / 2;

    float* out    = (float*)d_out;
    float* pooled = (float*)d_out + (size_t)n * OC;

    int smem = (IN_DIM * WS_S + IN_DIM * XS_S) * sizeof(float);  // ~100 KB
    cudaFuncSetAttribute(k_gemm, cudaFuncAttributeMaxDynamicSharedMemorySize, smem);

    k_detect<<<1, 32>>>((const unsigned*)ei);
    k_zero<<<(n + 255) / 256, 256>>>(n);
    k_watt<<<4, 256>>>(W, att_src, att_dst);
    k_gemm<<<(n + TM - 1) / TM, 256, smem>>>(x, W, n);
    k_count<<<(e + 255) / 256, 256>>>(ei, e);
    k_scan<<<1, 1024>>>(n);
    k_fill<<<(e + 255) / 256, 256>>>(ei, e);
    k_agg<<<(n + 7) / 8, 256>>>(bias, out, n);
    k_pooled<<<(e + 255) / 256, 256>>>(ei, pooled, e);
}

// round 10
// speedup vs baseline: 1.0439x; 1.0439x over previous
#include <cuda_runtime.h>
#include <cstdint>

#define N_MAX 50000
#define E_MAX 800000
#define IN_DIM 128
#define HEADS 4
#define OUT_DIM 32
#define OC (HEADS*OUT_DIM)   // 128
#define NEG_SLOPE 0.2f
#define EPS_F 1e-16f

// ---------------- scratch (no allocations allowed; 16B-aligned) ----------------
__device__ __align__(16) float g_h[N_MAX * OC];          // 25.6 MB
__device__ __align__(16) float g_asrc[N_MAX * HEADS];
__device__ __align__(16) float g_adst[N_MAX * HEADS];
__device__ __align__(16) float g_sinv[N_MAX * HEADS];    // 1/(sum+eps)
__device__ __align__(16) float g_wa[8 * IN_DIM];         // W^T * {att_src(4), att_dst(4)}
__device__ __align__(16) int   g_deg[N_MAX];
__device__ __align__(16) int   g_cur[N_MAX];
__device__ __align__(16) int   g_off[N_MAX + 1];
__device__ __align__(16) int   g_csr_src[E_MAX];
__device__ int g_idx64;   // 1 if edge_index is int64, 0 if int32

// ---------------- helpers ----------------
__device__ __forceinline__ float lrelu(float a) {
    return a > 0.f ? a : NEG_SLOPE * a;
}
__device__ __forceinline__ int2 load_edge(const void* ei, int e, int eidx) {
    if (g_idx64) {
        const long long* p = (const long long*)ei;
        return make_int2((int)p[eidx], (int)p[e + eidx]);
    } else {
        const int* p = (const int*)ei;
        return make_int2(p[eidx], p[e + eidx]);
    }
}

// ---------------- K detect: edge_index dtype ----------------
__global__ void k_detect(const unsigned* __restrict__ raw) {
    unsigned any = 0;
    for (int i = threadIdx.x; i < 128; i += 32) any |= raw[2 * i + 1];
#pragma unroll
    for (int o = 16; o > 0; o >>= 1) any |= __shfl_down_sync(0xffffffffu, any, o);
    if (threadIdx.x == 0) g_idx64 = (any == 0u) ? 1 : 0;
}

// ---------------- K zero: counters ----------------
__global__ void k_zero(int n) {
    int idx = blockIdx.x * blockDim.x + threadIdx.x;
    if (idx < n) { g_deg[idx] = 0; g_cur[idx] = 0; }
}

// ---------------- K watt: wa[j][k] = sum_d att[j%4][d] * W[( (j%4)*32+d )*128 + k] ----------------
__global__ void k_watt(const float* __restrict__ W, const float* __restrict__ att_src,
                       const float* __restrict__ att_dst) {
    int idx = threadIdx.x + blockIdx.x * blockDim.x;   // 1024 threads
    if (idx >= 8 * IN_DIM) return;
    int j = idx >> 7;          // 0..7
    int k = idx & 127;
    int hd = j & 3;
    const float* att = (j >= 4) ? att_dst : att_src;
    float s = 0.f;
#pragma unroll 8
    for (int d = 0; d < OUT_DIM; d++)
        s = fmaf(att[hd * OUT_DIM + d], W[(hd * OUT_DIM + d) * IN_DIM + k], s);
    g_wa[j * IN_DIM + k] = s;
}

// ---------------- K1: h = x @ W^T + attention projections (K-chunked, 4 CTAs/SM) ----------------
#define TM 64
#define KC 64
#define NCH (IN_DIM / KC)
#define WS_S 132
#define XS_S 68
#define WAS_S 132
// smem: ws[KC*WS_S] (33.8KB) + xs[KC*XS_S] (17.4KB) + was[8*WAS_S] (4.2KB) = 55.4KB
__global__ void __launch_bounds__(256, 4) k_gemm(const float* __restrict__ x,
                                                 const float* __restrict__ W, int n) {
    extern __shared__ float sm[];
    float* ws  = sm;                      // [KC][WS_S]
    float* xs  = sm + KC * WS_S;          // [KC][XS_S]
    float* was = xs + KC * XS_S;          // [8][WAS_S]
    int tid = threadIdx.x;
    int tx = tid & 15, ty = tid >> 4;
    int row0 = blockIdx.x * TM;
    int r = tid >> 2, hp = tid & 3;       // epilogue mapping: 64 rows x 4 heads

    for (int idx = tid; idx < 8 * IN_DIM; idx += 256) {
        int j = idx >> 7, k = idx & 127;
        was[j * WAS_S + k] = g_wa[idx];
    }

    float acc[4][8];
#pragma unroll
    for (int i = 0; i < 4; i++)
#pragma unroll
        for (int j = 0; j < 8; j++) acc[i][j] = 0.f;
    float s_ = 0.f, d_ = 0.f;

    for (int kc = 0; kc < NCH; kc++) {
        int k0 = kc * KC;
        __syncthreads();   // previous chunk's reads done (also covers was writes 1st iter)
        // load W chunk: ws[k][c] = W[c][k0+k]
        for (int idx = tid; idx < OC * KC; idx += 256) {
            int c = idx >> 6, k = idx & 63;
            ws[k * WS_S + c] = W[c * IN_DIM + k0 + k];
        }
        // load x chunk: xs[k][r] = x[row0+r][k0+k]
        for (int idx = tid; idx < TM * KC; idx += 256) {
            int rr = idx >> 6, k = idx & 63;
            int row = row0 + rr;
            xs[k * XS_S + rr] = (row < n) ? x[row * IN_DIM + k0 + k] : 0.f;
        }
        __syncthreads();

#pragma unroll 8
        for (int k = 0; k < KC; k++) {
            float4 a  = *(const float4*)&xs[k * XS_S + ty * 4];
            float4 b0 = *(const float4*)&ws[k * WS_S + tx * 8];
            float4 b1 = *(const float4*)&ws[k * WS_S + tx * 8 + 4];
            float av[4] = {a.x, a.y, a.z, a.w};
            float bv[8] = {b0.x, b0.y, b0.z, b0.w, b1.x, b1.y, b1.z, b1.w};
#pragma unroll
            for (int i = 0; i < 4; i++)
#pragma unroll
                for (int j = 0; j < 8; j++) acc[i][j] = fmaf(av[i], bv[j], acc[i][j]);
        }

        // attention-projection partial over this chunk (reads only; no sync needed)
#pragma unroll 8
        for (int k = 0; k < KC; k++) {
            float xv = xs[k * XS_S + r];
            s_ = fmaf(xv, was[hp * WAS_S + k0 + k], s_);
            d_ = fmaf(xv, was[(hp + 4) * WAS_S + k0 + k], d_);
        }
    }

#pragma unroll
    for (int i = 0; i < 4; i++) {
        int row = row0 + ty * 4 + i;
        if (row < n) {
            *(float4*)&g_h[row * OC + tx * 8]     = make_float4(acc[i][0], acc[i][1], acc[i][2], acc[i][3]);
            *(float4*)&g_h[row * OC + tx * 8 + 4] = make_float4(acc[i][4], acc[i][5], acc[i][6], acc[i][7]);
        }
    }
    int prow = row0 + r;
    if (prow < n) {
        g_asrc[prow * HEADS + hp] = s_;
        g_adst[prow * HEADS + hp] = d_;
    }
}

// ---------------- CSR build ----------------
__global__ void k_count(const void* __restrict__ ei, int e) {
    int eidx = blockIdx.x * blockDim.x + threadIdx.x;
    if (eidx >= e) return;
    int dst = (g_idx64) ? (int)((const long long*)ei)[e + eidx]
                        : ((const int*)ei)[e + eidx];
    atomicAdd(&g_deg[dst], 1);
}

__global__ void k_scan(int n) {   // single block, 1024 threads; exclusive scan of g_deg -> g_off
    __shared__ int warpsum[32];
    int tid = threadIdx.x;
    int chunk = (n + 1023) / 1024;
    int beg = tid * chunk;
    int end = min(beg + chunk, n);
    int s = 0;
    for (int i = beg; i < end; i++) s += g_deg[i];
    int lane = tid & 31, wid = tid >> 5;
    int v = s;
#pragma unroll
    for (int o = 1; o < 32; o <<= 1) {
        int t = __shfl_up_sync(0xffffffffu, v, o);
        if (lane >= o) v += t;
    }
    if (lane == 31) warpsum[wid] = v;
    __syncthreads();
    if (wid == 0) {
        int w = warpsum[lane];
#pragma unroll
        for (int o = 1; o < 32; o <<= 1) {
            int t = __shfl_up_sync(0xffffffffu, w, o);
            if (lane >= o) w += t;
        }
        warpsum[lane] = w;
    }
    __syncthreads();
    int base = ((wid > 0) ? warpsum[wid - 1] : 0) + (v - s);
    int run = base;
    for (int i = beg; i < end; i++) { g_off[i] = run; run += g_deg[i]; }
    if (tid == 0) g_off[n] = warpsum[31];
}

__global__ void k_fill(const void* __restrict__ ei, int e) {
    int eidx = blockIdx.x * blockDim.x + threadIdx.x;
    if (eidx >= e) return;
    int2 sd = load_edge(ei, e, eidx);
    int pos = g_off[sd.y] + atomicAdd(&g_cur[sd.y], 1);
    g_csr_src[pos] = sd.x;
}

// ---------------- K agg: one warp per dst node, register accumulation, no atomics ----------------
__global__ void k_agg(const float* __restrict__ bias, float* __restrict__ out, int n) {
    int w = blockIdx.x * (blockDim.x >> 5) + (threadIdx.x >> 5);
    if (w >= n) return;
    int lane = threadIdx.x & 31;
    int hd = lane >> 3;

    int off = g_off[w];
    int deg = g_off[w + 1] - off;

    float ad = g_adst[w * HEADS + hd];
    float4 acc = make_float4(0.f, 0.f, 0.f, 0.f);
    float ssum = 0.f;

    int i = 0;
    for (; i + 3 < deg; i += 4) {
        int s0 = g_csr_src[off + i];
        int s1 = g_csr_src[off + i + 1];
        int s2 = g_csr_src[off + i + 2];
        int s3 = g_csr_src[off + i + 3];
        float ex0 = __expf(lrelu(g_asrc[s0 * HEADS + hd] + ad));
        float ex1 = __expf(lrelu(g_asrc[s1 * HEADS + hd] + ad));
        float ex2 = __expf(lrelu(g_asrc[s2 * HEADS + hd] + ad));
        float ex3 = __expf(lrelu(g_asrc[s3 * HEADS + hd] + ad));
        float4 v0 = *(const float4*)&g_h[s0 * OC + lane * 4];
        float4 v1 = *(const float4*)&g_h[s1 * OC + lane * 4];
        float4 v2 = *(const float4*)&g_h[s2 * OC + lane * 4];
        float4 v3 = *(const float4*)&g_h[s3 * OC + lane * 4];
        ssum += (ex0 + ex1) + (ex2 + ex3);
        acc.x = fmaf(ex0, v0.x, fmaf(ex1, v1.x, fmaf(ex2, v2.x, fmaf(ex3, v3.x, acc.x))));
        acc.y = fmaf(ex0, v0.y, fmaf(ex1, v1.y, fmaf(ex2, v2.y, fmaf(ex3, v3.y, acc.y))));
        acc.z = fmaf(ex0, v0.z, fmaf(ex1, v1.z, fmaf(ex2, v2.z, fmaf(ex3, v3.z, acc.z))));
        acc.w = fmaf(ex0, v0.w, fmaf(ex1, v1.w, fmaf(ex2, v2.w, fmaf(ex3, v3.w, acc.w))));
    }
    for (; i < deg; i++) {
        int s0 = g_csr_src[off + i];
        float ex0 = __expf(lrelu(g_asrc[s0 * HEADS + hd] + ad));
        float4 v0 = *(const float4*)&g_h[s0 * OC + lane * 4];
        ssum += ex0;
        acc.x = fmaf(ex0, v0.x, acc.x);
        acc.y = fmaf(ex0, v0.y, acc.y);
        acc.z = fmaf(ex0, v0.z, acc.z);
        acc.w = fmaf(ex0, v0.w, acc.w);
    }

    float inv = 1.f / (ssum + EPS_F);
    float4 b = *(const float4*)&bias[lane * 4];
    acc.x = fmaf(acc.x, inv, b.x);
    acc.y = fmaf(acc.y, inv, b.y);
    acc.z = fmaf(acc.z, inv, b.z);
    acc.w = fmaf(acc.w, inv, b.w);
    *(float4*)&out[w * OC + lane * 4] = acc;

    if ((lane & 7) == 0) g_sinv[w * HEADS + hd] = inv;
}

// ---------------- K pooled: one thread per edge (multiply by precomputed 1/s) ----------------
__global__ void k_pooled(const void* __restrict__ ei, float* __restrict__ pooled, int e) {
    int eidx = blockIdx.x * blockDim.x + threadIdx.x;
    if (eidx >= e) return;
    int2 sd = load_edge(ei, e, eidx);
    float4 as = *(const float4*)&g_asrc[sd.x * HEADS];
    float4 ad = *(const float4*)&g_adst[sd.y * HEADS];
    float4 sv = *(const float4*)&g_sinv[sd.y * HEADS];
    float p = __expf(lrelu(as.x + ad.x)) * sv.x
            + __expf(lrelu(as.y + ad.y)) * sv.y
            + __expf(lrelu(as.z + ad.z)) * sv.z
            + __expf(lrelu(as.w + ad.w)) * sv.w;
    pooled[eidx] = p * 0.25f;
}

// ---------------- launch ----------------
extern "C" void kernel_launch(void* const* d_in, const int* in_sizes, int n_in,
                              void* d_out, int out_size) {
    const float* x       = (const float*)d_in[0];
    const void*  ei      = d_in[1];
    const float* W       = (const float*)d_in[2];
    const float* att_src = (const float*)d_in[3];
    const float* att_dst = (const float*)d_in[4];
    const float* bias    = (const float*)d_in[5];

    int n = in_sizes[0] / IN_DIM;
    int e = in_sizes[1] / 2;

    float* out    = (float*)d_out;
    float* pooled = (float*)d_out + (size_t)n * OC;

    int smem = (KC * WS_S + KC * XS_S + 8 * WAS_S) * sizeof(float);  // ~55.4 KB
    cudaFuncSetAttribute(k_gemm, cudaFuncAttributeMaxDynamicSharedMemorySize, smem);

    k_detect<<<1, 32>>>((const unsigned*)ei);
    k_zero<<<(n + 255) / 256, 256>>>(n);
    k_watt<<<4, 256>>>(W, att_src, att_dst);
    k_gemm<<<(n + TM - 1) / TM, 256, smem>>>(x, W, n);
    k_count<<<(e + 255) / 256, 256>>>(ei, e);
    k_scan<<<1, 1024>>>(n);
    k_fill<<<(e + 255) / 256, 256>>>(ei, e);
    k_agg<<<(n + 7) / 8, 256>>>(bias, out, n);
    k_pooled<<<(e + 255) / 256, 256>>>(ei, pooled, e);
}

// round 12
// speedup vs baseline: 1.3902x; 1.3317x over previous
#include <cuda_runtime.h>
#include <cstdint>

#define N_MAX 50000
#define E_MAX 800000
#define IN_DIM 128
#define HEADS 4
#define OUT_DIM 32
#define OC (HEADS*OUT_DIM)   // 128
#define NEG_SLOPE 0.2f
#define EPS_F 1e-16f

// ---------------- scratch (no allocations allowed; 16B-aligned) ----------------
__device__ __align__(16) float g_h[N_MAX * OC];          // 25.6 MB
__device__ __align__(16) float g_asrc[N_MAX * HEADS];
__device__ __align__(16) float g_adst[N_MAX * HEADS];
__device__ __align__(16) float g_sinv[N_MAX * HEADS];    // 1/(sum+eps)
__device__ __align__(16) float g_wa[8 * IN_DIM];         // W^T * {att_src(4), att_dst(4)}
__device__ __align__(16) int   g_deg[N_MAX];
__device__ __align__(16) int   g_cur[N_MAX];
__device__ __align__(16) int   g_off[N_MAX + 1];
__device__ __align__(16) int   g_csr_src[E_MAX];
__device__ int g_idx64;   // 1 if edge_index is int64, 0 if int32

// ---------------- helpers ----------------
__device__ __forceinline__ float lrelu(float a) {
    return a > 0.f ? a : NEG_SLOPE * a;
}
__device__ __forceinline__ int2 load_edge(const void* ei, int e, int eidx) {
    if (g_idx64) {
        const long long* p = (const long long*)ei;
        return make_int2((int)p[eidx], (int)p[e + eidx]);
    } else {
        const int* p = (const int*)ei;
        return make_int2(p[eidx], p[e + eidx]);
    }
}
__device__ __forceinline__ float f2tf32(float f) {
    unsigned u;
    asm("cvt.rna.tf32.f32 %0, %1;" : "=r"(u) : "f"(f));
    return __uint_as_float(u);
}
__device__ __forceinline__ void mma_tf32(float* c, const float* a, float b0, float b1) {
    asm volatile(
        "mma.sync.aligned.m16n8k8.row.col.f32.tf32.tf32.f32 "
        "{%0,%1,%2,%3}, {%4,%5,%6,%7}, {%8,%9}, {%0,%1,%2,%3};"
        : "+f"(c[0]), "+f"(c[1]), "+f"(c[2]), "+f"(c[3])
        : "r"(__float_as_uint(a[0])), "r"(__float_as_uint(a[1])),
          "r"(__float_as_uint(a[2])), "r"(__float_as_uint(a[3])),
          "r"(__float_as_uint(b0)),  "r"(__float_as_uint(b1)));
}

// ---------------- K detect: edge_index dtype ----------------
__global__ void k_detect(const unsigned* __restrict__ raw) {
    unsigned any = 0;
    for (int i = threadIdx.x; i < 128; i += 32) any |= raw[2 * i + 1];
#pragma unroll
    for (int o = 16; o > 0; o >>= 1) any |= __shfl_down_sync(0xffffffffu, any, o);
    if (threadIdx.x == 0) g_idx64 = (any == 0u) ? 1 : 0;
}

// ---------------- K zero: counters ----------------
__global__ void k_zero(int n) {
    int idx = blockIdx.x * blockDim.x + threadIdx.x;
    if (idx < n) { g_deg[idx] = 0; g_cur[idx] = 0; }
}

// ---------------- K watt: wa[j][k] = sum_d att[j%4][d] * W[((j%4)*32+d)*128 + k] ----------------
__global__ void k_watt(const float* __restrict__ W, const float* __restrict__ att_src,
                       const float* __restrict__ att_dst) {
    int idx = threadIdx.x + blockIdx.x * blockDim.x;
    if (idx >= 8 * IN_DIM) return;
    int j = idx >> 7;
    int k = idx & 127;
    int hd = j & 3;
    const float* att = (j >= 4) ? att_dst : att_src;
    float s = 0.f;
#pragma unroll 8
    for (int d = 0; d < OUT_DIM; d++)
        s = fmaf(att[hd * OUT_DIM + d], W[(hd * OUT_DIM + d) * IN_DIM + k], s);
    g_wa[j * IN_DIM + k] = s;
}

// ---------------- K1: h = x @ W^T via TF32 tensor cores (3-term compensated) ----------------
// Block: 256 thr = 8 warps. Tile: 64 rows x 128 cols. Warp: 32 rows x 32 cols.
// K chunked by 32. smem strides padded to 36 for conflict-free fragment gathers.
#define TM 64
#define GKC 32
#define XP 36
// smem floats: xs_h/xs_l: 64*36 each; ws_h/ws_l: 128*36 each; was: 8*132
#define SM_XS (TM * XP)
#define SM_WS (OC * XP)
#define WAS_S 132
__global__ void __launch_bounds__(256) k_gemm(const float* __restrict__ x,
                                              const float* __restrict__ W, int n) {
    extern __shared__ float sm[];
    float* xs_h = sm;
    float* xs_l = xs_h + SM_XS;
    float* ws_h = xs_l + SM_XS;
    float* ws_l = ws_h + SM_WS;
    float* was  = ws_l + SM_WS;      // [8][WAS_S]

    int tid = threadIdx.x;
    int wid = tid >> 5, lane = tid & 31;
    int gid = lane >> 2, tig = lane & 3;
    int wm = wid & 1, wn = wid >> 1;         // warp tile: rows wm*32, cols wn*32
    int row0 = blockIdx.x * TM;
    int pr = tid >> 2, hp = tid & 3;         // attproj mapping: 64 rows x 4 heads

    for (int idx = tid; idx < 8 * IN_DIM; idx += 256) {
        int j = idx >> 7, k = idx & 127;
        was[j * WAS_S + k] = g_wa[idx];
    }

    float c[2][4][4];
#pragma unroll
    for (int mt = 0; mt < 2; mt++)
#pragma unroll
        for (int nt = 0; nt < 4; nt++)
#pragma unroll
            for (int j = 0; j < 4; j++) c[mt][nt][j] = 0.f;
    float s_ = 0.f, d_ = 0.f;

    for (int kc = 0; kc < IN_DIM / GKC; kc++) {
        int k0 = kc * GKC;
        __syncthreads();
        // load x chunk: 64 rows x 32 k  (512 float4s, 2 per thread)
        for (int t = tid; t < TM * (GKC / 4); t += 256) {
            int r = t >> 3, kk = (t & 7) * 4;
            int row = row0 + r;
            float4 v = (row < n) ? *(const float4*)&x[(size_t)row * IN_DIM + k0 + kk]
                                 : make_float4(0.f, 0.f, 0.f, 0.f);
            float h0 = f2tf32(v.x), h1 = f2tf32(v.y), h2 = f2tf32(v.z), h3 = f2tf32(v.w);
            *(float4*)&xs_h[r * XP + kk] = make_float4(h0, h1, h2, h3);
            *(float4*)&xs_l[r * XP + kk] = make_float4(f2tf32(v.x - h0), f2tf32(v.y - h1),
                                                       f2tf32(v.z - h2), f2tf32(v.w - h3));
        }
        // load W chunk: 128 cols x 32 k  (1024 float4s, 4 per thread)
        for (int t = tid; t < OC * (GKC / 4); t += 256) {
            int cc = t >> 3, kk = (t & 7) * 4;
            float4 v = *(const float4*)&W[cc * IN_DIM + k0 + kk];
            float h0 = f2tf32(v.x), h1 = f2tf32(v.y), h2 = f2tf32(v.z), h3 = f2tf32(v.w);
            *(float4*)&ws_h[cc * XP + kk] = make_float4(h0, h1, h2, h3);
            *(float4*)&ws_l[cc * XP + kk] = make_float4(f2tf32(v.x - h0), f2tf32(v.y - h1),
                                                        f2tf32(v.z - h2), f2tf32(v.w - h3));
        }
        __syncthreads();

#pragma unroll
        for (int ks = 0; ks < GKC / 8; ks++) {
            int kk = ks * 8;
            float ah[2][4], al[2][4];
#pragma unroll
            for (int mt = 0; mt < 2; mt++) {
                int r = wm * 32 + mt * 16 + gid;
                ah[mt][0] = xs_h[r * XP + kk + tig];
                ah[mt][1] = xs_h[(r + 8) * XP + kk + tig];
                ah[mt][2] = xs_h[r * XP + kk + tig + 4];
                ah[mt][3] = xs_h[(r + 8) * XP + kk + tig + 4];
                al[mt][0] = xs_l[r * XP + kk + tig];
                al[mt][1] = xs_l[(r + 8) * XP + kk + tig];
                al[mt][2] = xs_l[r * XP + kk + tig + 4];
                al[mt][3] = xs_l[(r + 8) * XP + kk + tig + 4];
            }
#pragma unroll
            for (int nt = 0; nt < 4; nt++) {
                int cn = wn * 32 + nt * 8 + gid;
                float bh0 = ws_h[cn * XP + kk + tig];
                float bh1 = ws_h[cn * XP + kk + tig + 4];
                float bl0 = ws_l[cn * XP + kk + tig];
                float bl1 = ws_l[cn * XP + kk + tig + 4];
#pragma unroll
                for (int mt = 0; mt < 2; mt++) {
                    mma_tf32(c[mt][nt], ah[mt], bh0, bh1);
                    mma_tf32(c[mt][nt], ah[mt], bl0, bl1);
                    mma_tf32(c[mt][nt], al[mt], bh0, bh1);
                }
            }
        }

        // attention-projection partial over this chunk (xs hi+lo = exact x)
#pragma unroll 8
        for (int k = 0; k < GKC; k++) {
            float xv = xs_h[pr * XP + k] + xs_l[pr * XP + k];
            s_ = fmaf(xv, was[hp * WAS_S + k0 + k], s_);
            d_ = fmaf(xv, was[(hp + 4) * WAS_S + k0 + k], d_);
        }
    }

    // store C: c[mt][nt]: rows row0+wm*32+mt*16+gid(+8), cols wn*32+nt*8+2*tig(+1)
#pragma unroll
    for (int mt = 0; mt < 2; mt++) {
#pragma unroll
        for (int nt = 0; nt < 4; nt++) {
            int row = row0 + wm * 32 + mt * 16 + gid;
            int col = wn * 32 + nt * 8 + tig * 2;
            if (row < n)
                *(float2*)&g_h[(size_t)row * OC + col] = make_float2(c[mt][nt][0], c[mt][nt][1]);
            if (row + 8 < n)
                *(float2*)&g_h[(size_t)(row + 8) * OC + col] = make_float2(c[mt][nt][2], c[mt][nt][3]);
        }
    }
    int prow = row0 + pr;
    if (prow < n) {
        g_asrc[prow * HEADS + hp] = s_;
        g_adst[prow * HEADS + hp] = d_;
    }
}

// ---------------- CSR build ----------------
__global__ void k_count(const void* __restrict__ ei, int e) {
    int eidx = blockIdx.x * blockDim.x + threadIdx.x;
    if (eidx >= e) return;
    int dst = (g_idx64) ? (int)((const long long*)ei)[e + eidx]
                        : ((const int*)ei)[e + eidx];
    atomicAdd(&g_deg[dst], 1);
}

__global__ void k_scan(int n) {   // single block, 1024 threads; exclusive scan of g_deg -> g_off
    __shared__ int warpsum[32];
    int tid = threadIdx.x;
    int chunk = (n + 1023) / 1024;
    int beg = tid * chunk;
    int end = min(beg + chunk, n);
    int s = 0;
    for (int i = beg; i < end; i++) s += g_deg[i];
    int lane = tid & 31, wid = tid >> 5;
    int v = s;
#pragma unroll
    for (int o = 1; o < 32; o <<= 1) {
        int t = __shfl_up_sync(0xffffffffu, v, o);
        if (lane >= o) v += t;
    }
    if (lane == 31) warpsum[wid] = v;
    __syncthreads();
    if (wid == 0) {
        int w = warpsum[lane];
#pragma unroll
        for (int o = 1; o < 32; o <<= 1) {
            int t = __shfl_up_sync(0xffffffffu, w, o);
            if (lane >= o) w += t;
        }
        warpsum[lane] = w;
    }
    __syncthreads();
    int base = ((wid > 0) ? warpsum[wid - 1] : 0) + (v - s);
    int run = base;
    for (int i = beg; i < end; i++) { g_off[i] = run; run += g_deg[i]; }
    if (tid == 0) g_off[n] = warpsum[31];
}

__global__ void k_fill(const void* __restrict__ ei, int e) {
    int eidx = blockIdx.x * blockDim.x + threadIdx.x;
    if (eidx >= e) return;
    int2 sd = load_edge(ei, e, eidx);
    int pos = g_off[sd.y] + atomicAdd(&g_cur[sd.y], 1);
    g_csr_src[pos] = sd.x;
}

// ---------------- K agg: one warp per dst node, register accumulation, no atomics ----------------
__global__ void k_agg(const float* __restrict__ bias, float* __restrict__ out, int n) {
    int w = blockIdx.x * (blockDim.x >> 5) + (threadIdx.x >> 5);
    if (w >= n) return;
    int lane = threadIdx.x & 31;
    int hd = lane >> 3;

    int off = g_off[w];
    int deg = g_off[w + 1] - off;

    float ad = g_adst[w * HEADS + hd];
    float4 acc = make_float4(0.f, 0.f, 0.f, 0.f);
    float ssum = 0.f;

    int i = 0;
    for (; i + 3 < deg; i += 4) {
        int s0 = g_csr_src[off + i];
        int s1 = g_csr_src[off + i + 1];
        int s2 = g_csr_src[off + i + 2];
        int s3 = g_csr_src[off + i + 3];
        float ex0 = __expf(lrelu(g_asrc[s0 * HEADS + hd] + ad));
        float ex1 = __expf(lrelu(g_asrc[s1 * HEADS + hd] + ad));
        float ex2 = __expf(lrelu(g_asrc[s2 * HEADS + hd] + ad));
        float ex3 = __expf(lrelu(g_asrc[s3 * HEADS + hd] + ad));
        float4 v0 = *(const float4*)&g_h[s0 * OC + lane * 4];
        float4 v1 = *(const float4*)&g_h[s1 * OC + lane * 4];
        float4 v2 = *(const float4*)&g_h[s2 * OC + lane * 4];
        float4 v3 = *(const float4*)&g_h[s3 * OC + lane * 4];
        ssum += (ex0 + ex1) + (ex2 + ex3);
        acc.x = fmaf(ex0, v0.x, fmaf(ex1, v1.x, fmaf(ex2, v2.x, fmaf(ex3, v3.x, acc.x))));
        acc.y = fmaf(ex0, v0.y, fmaf(ex1, v1.y, fmaf(ex2, v2.y, fmaf(ex3, v3.y, acc.y))));
        acc.z = fmaf(ex0, v0.z, fmaf(ex1, v1.z, fmaf(ex2, v2.z, fmaf(ex3, v3.z, acc.z))));
        acc.w = fmaf(ex0, v0.w, fmaf(ex1, v1.w, fmaf(ex2, v2.w, fmaf(ex3, v3.w, acc.w))));
    }
    for (; i < deg; i++) {
        int s0 = g_csr_src[off + i];
        float ex0 = __expf(lrelu(g_asrc[s0 * HEADS + hd] + ad));
        float4 v0 = *(const float4*)&g_h[s0 * OC + lane * 4];
        ssum += ex0;
        acc.x = fmaf(ex0, v0.x, acc.x);
        acc.y = fmaf(ex0, v0.y, acc.y);
        acc.z = fmaf(ex0, v0.z, acc.z);
        acc.w = fmaf(ex0, v0.w, acc.w);
    }

    float inv = 1.f / (ssum + EPS_F);
    float4 b = *(const float4*)&bias[lane * 4];
    acc.x = fmaf(acc.x, inv, b.x);
    acc.y = fmaf(acc.y, inv, b.y);
    acc.z = fmaf(acc.z, inv, b.z);
    acc.w = fmaf(acc.w, inv, b.w);
    *(float4*)&out[w * OC + lane * 4] = acc;

    if ((lane & 7) == 0) g_sinv[w * HEADS + hd] = inv;
}

// ---------------- K pooled: one thread per edge (multiply by precomputed 1/s) ----------------
__global__ void k_pooled(const void* __restrict__ ei, float* __restrict__ pooled, int e) {
    int eidx = blockIdx.x * blockDim.x + threadIdx.x;
    if (eidx >= e) return;
    int2 sd = load_edge(ei, e, eidx);
    float4 as = *(const float4*)&g_asrc[sd.x * HEADS];
    float4 ad = *(const float4*)&g_adst[sd.y * HEADS];
    float4 sv = *(const float4*)&g_sinv[sd.y * HEADS];
    float p = __expf(lrelu(as.x + ad.x)) * sv.x
            + __expf(lrelu(as.y + ad.y)) * sv.y
            + __expf(lrelu(as.z + ad.z)) * sv.z
            + __expf(lrelu(as.w + ad.w)) * sv.w;
    pooled[eidx] = p * 0.25f;
}

// ---------------- launch ----------------
extern "C" void kernel_launch(void* const* d_in, const int* in_sizes, int n_in,
                              void* d_out, int out_size) {
    const float* x       = (const float*)d_in[0];
    const void*  ei      = d_in[1];
    const float* W       = (const float*)d_in[2];
    const float* att_src = (const float*)d_in[3];
    const float* att_dst = (const float*)d_in[4];
    const float* bias    = (const float*)d_in[5];

    int n = in_sizes[0] / IN_DIM;
    int e = in_sizes[1] / 2;

    float* out    = (float*)d_out;
    float* pooled = (float*)d_out + (size_t)n * OC;

    int smem = (2 * SM_XS + 2 * SM_WS + 8 * WAS_S) * sizeof(float);  // ~59.7 KB
    cudaFuncSetAttribute(k_gemm, cudaFuncAttributeMaxDynamicSharedMemorySize, smem);

    k_detect<<<1, 32>>>((const unsigned*)ei);
    k_zero<<<(n + 255) / 256, 256>>>(n);
    k_watt<<<4, 256>>>(W, att_src, att_dst);
    k_gemm<<<(n + TM - 1) / TM, 256, smem>>>(x, W, n);
    k_count<<<(e + 255) / 256, 256>>>(ei, e);
    k_scan<<<1, 1024>>>(n);
    k_fill<<<(e + 255) / 256, 256>>>(ei, e);
    k_agg<<<(n + 7) / 8, 256>>>(bias, out, n);
    k_pooled<<<(e + 255) / 256, 256>>>(ei, pooled, e);
}

// round 14
// speedup vs baseline: 1.4267x; 1.0262x over previous
#include <cuda_runtime.h>
#include <cuda_fp16.h>
#include <cstdint>

#define N_MAX 50000
#define E_MAX 800000
#define IN_DIM 128
#define HEADS 4
#define OUT_DIM 32
#define OC (HEADS*OUT_DIM)   // 128
#define NEG_SLOPE 0.2f
#define EPS_F 1e-16f

// ---------------- scratch (no allocations allowed; 16B-aligned) ----------------
__device__ __align__(16) __half g_hh[N_MAX * OC];        // 12.8 MB (fp16 h)
__device__ __align__(16) float g_asrc[N_MAX * HEADS];
__device__ __align__(16) float g_adst[N_MAX * HEADS];
__device__ __align__(16) float g_wa[8 * IN_DIM];         // W^T * {att_src(4), att_dst(4)}
__device__ __align__(16) int   g_deg[N_MAX];
__device__ __align__(16) int   g_cur[N_MAX];
__device__ __align__(16) int   g_off[N_MAX + 1];
__device__ __align__(16) int   g_csr_src[E_MAX];
__device__ __align__(16) int   g_csr_eid[E_MAX];
__device__ int g_idx64;   // 1 if edge_index is int64, 0 if int32

// ---------------- helpers ----------------
__device__ __forceinline__ float lrelu(float a) {
    return a > 0.f ? a : NEG_SLOPE * a;
}
__device__ __forceinline__ int2 load_edge(const void* ei, int e, int eidx) {
    if (g_idx64) {
        const long long* p = (const long long*)ei;
        return make_int2((int)p[eidx], (int)p[e + eidx]);
    } else {
        const int* p = (const int*)ei;
        return make_int2(p[eidx], p[e + eidx]);
    }
}
__device__ __forceinline__ float f2tf32(float f) {
    unsigned u;
    asm("cvt.rna.tf32.f32 %0, %1;" : "=r"(u) : "f"(f));
    return __uint_as_float(u);
}
__device__ __forceinline__ void mma_tf32(float* c, const float* a, float b0, float b1) {
    asm volatile(
        "mma.sync.aligned.m16n8k8.row.col.f32.tf32.tf32.f32 "
        "{%0,%1,%2,%3}, {%4,%5,%6,%7}, {%8,%9}, {%0,%1,%2,%3};"
        : "+f"(c[0]), "+f"(c[1]), "+f"(c[2]), "+f"(c[3])
        : "r"(__float_as_uint(a[0])), "r"(__float_as_uint(a[1])),
          "r"(__float_as_uint(a[2])), "r"(__float_as_uint(a[3])),
          "r"(__float_as_uint(b0)),  "r"(__float_as_uint(b1)));
}
// load 4 consecutive fp16 h values as float4 (8B load)
__device__ __forceinline__ float4 ld_h4(const __half* p) {
    uint2 u = *(const uint2*)p;
    __half2 h0 = *(__half2*)&u.x, h1 = *(__half2*)&u.y;
    float2 f0 = __half22float2(h0), f1 = __half22float2(h1);
    return make_float4(f0.x, f0.y, f1.x, f1.y);
}

// ---------------- K detect: edge_index dtype ----------------
__global__ void k_detect(const unsigned* __restrict__ raw) {
    unsigned any = 0;
    for (int i = threadIdx.x; i < 128; i += 32) any |= raw[2 * i + 1];
#pragma unroll
    for (int o = 16; o > 0; o >>= 1) any |= __shfl_down_sync(0xffffffffu, any, o);
    if (threadIdx.x == 0) g_idx64 = (any == 0u) ? 1 : 0;
}

// ---------------- K zero: counters ----------------
__global__ void k_zero(int n) {
    int idx = blockIdx.x * blockDim.x + threadIdx.x;
    if (idx < n) { g_deg[idx] = 0; g_cur[idx] = 0; }
}

// ---------------- K watt: wa[j][k] = sum_d att[j%4][d] * W[((j%4)*32+d)*128 + k] ----------------
__global__ void k_watt(const float* __restrict__ W, const float* __restrict__ att_src,
                       const float* __restrict__ att_dst) {
    int idx = threadIdx.x + blockIdx.x * blockDim.x;
    if (idx >= 8 * IN_DIM) return;
    int j = idx >> 7;
    int k = idx & 127;
    int hd = j & 3;
    const float* att = (j >= 4) ? att_dst : att_src;
    float s = 0.f;
#pragma unroll 8
    for (int d = 0; d < OUT_DIM; d++)
        s = fmaf(att[hd * OUT_DIM + d], W[(hd * OUT_DIM + d) * IN_DIM + k], s);
    g_wa[j * IN_DIM + k] = s;
}

// ---------------- K1: h = x @ W^T via TF32 tensor cores (3-term compensated), fp16 out ----------------
#define TM 64
#define GKC 32
#define XP 36
#define SM_XS (TM * XP)
#define SM_WS (OC * XP)
#define WAS_S 132
__global__ void __launch_bounds__(256) k_gemm(const float* __restrict__ x,
                                              const float* __restrict__ W, int n) {
    extern __shared__ float sm[];
    float* xs_h = sm;
    float* xs_l = xs_h + SM_XS;
    float* ws_h = xs_l + SM_XS;
    float* ws_l = ws_h + SM_WS;
    float* was  = ws_l + SM_WS;      // [8][WAS_S]

    int tid = threadIdx.x;
    int wid = tid >> 5, lane = tid & 31;
    int gid = lane >> 2, tig = lane & 3;
    int wm = wid & 1, wn = wid >> 1;
    int row0 = blockIdx.x * TM;
    int pr = tid >> 2, hp = tid & 3;

    for (int idx = tid; idx < 8 * IN_DIM; idx += 256) {
        int j = idx >> 7, k = idx & 127;
        was[j * WAS_S + k] = g_wa[idx];
    }

    float c[2][4][4];
#pragma unroll
    for (int mt = 0; mt < 2; mt++)
#pragma unroll
        for (int nt = 0; nt < 4; nt++)
#pragma unroll
            for (int j = 0; j < 4; j++) c[mt][nt][j] = 0.f;
    float s_ = 0.f, d_ = 0.f;

    for (int kc = 0; kc < IN_DIM / GKC; kc++) {
        int k0 = kc * GKC;
        __syncthreads();
        for (int t = tid; t < TM * (GKC / 4); t += 256) {
            int r = t >> 3, kk = (t & 7) * 4;
            int row = row0 + r;
            float4 v = (row < n) ? *(const float4*)&x[(size_t)row * IN_DIM + k0 + kk]
                                 : make_float4(0.f, 0.f, 0.f, 0.f);
            float h0 = f2tf32(v.x), h1 = f2tf32(v.y), h2 = f2tf32(v.z), h3 = f2tf32(v.w);
            *(float4*)&xs_h[r * XP + kk] = make_float4(h0, h1, h2, h3);
            *(float4*)&xs_l[r * XP + kk] = make_float4(f2tf32(v.x - h0), f2tf32(v.y - h1),
                                                       f2tf32(v.z - h2), f2tf32(v.w - h3));
        }
        for (int t = tid; t < OC * (GKC / 4); t += 256) {
            int cc = t >> 3, kk = (t & 7) * 4;
            float4 v = *(const float4*)&W[cc * IN_DIM + k0 + kk];
            float h0 = f2tf32(v.x), h1 = f2tf32(v.y), h2 = f2tf32(v.z), h3 = f2tf32(v.w);
            *(float4*)&ws_h[cc * XP + kk] = make_float4(h0, h1, h2, h3);
            *(float4*)&ws_l[cc * XP + kk] = make_float4(f2tf32(v.x - h0), f2tf32(v.y - h1),
                                                        f2tf32(v.z - h2), f2tf32(v.w - h3));
        }
        __syncthreads();

#pragma unroll
        for (int ks = 0; ks < GKC / 8; ks++) {
            int kk = ks * 8;
            float ah[2][4], al[2][4];
#pragma unroll
            for (int mt = 0; mt < 2; mt++) {
                int r = wm * 32 + mt * 16 + gid;
                ah[mt][0] = xs_h[r * XP + kk + tig];
                ah[mt][1] = xs_h[(r + 8) * XP + kk + tig];
                ah[mt][2] = xs_h[r * XP + kk + tig + 4];
                ah[mt][3] = xs_h[(r + 8) * XP + kk + tig + 4];
                al[mt][0] = xs_l[r * XP + kk + tig];
                al[mt][1] = xs_l[(r + 8) * XP + kk + tig];
                al[mt][2] = xs_l[r * XP + kk + tig + 4];
                al[mt][3] = xs_l[(r + 8) * XP + kk + tig + 4];
            }
#pragma unroll
            for (int nt = 0; nt < 4; nt++) {
                int cn = wn * 32 + nt * 8 + gid;
                float bh0 = ws_h[cn * XP + kk + tig];
                float bh1 = ws_h[cn * XP + kk + tig + 4];
                float bl0 = ws_l[cn * XP + kk + tig];
                float bl1 = ws_l[cn * XP + kk + tig + 4];
#pragma unroll
                for (int mt = 0; mt < 2; mt++) {
                    mma_tf32(c[mt][nt], ah[mt], bh0, bh1);
                    mma_tf32(c[mt][nt], ah[mt], bl0, bl1);
                    mma_tf32(c[mt][nt], al[mt], bh0, bh1);
                }
            }
        }

#pragma unroll 8
        for (int k = 0; k < GKC; k++) {
            float xv = xs_h[pr * XP + k] + xs_l[pr * XP + k];
            s_ = fmaf(xv, was[hp * WAS_S + k0 + k], s_);
            d_ = fmaf(xv, was[(hp + 4) * WAS_S + k0 + k], d_);
        }
    }

#pragma unroll
    for (int mt = 0; mt < 2; mt++) {
#pragma unroll
        for (int nt = 0; nt < 4; nt++) {
            int row = row0 + wm * 32 + mt * 16 + gid;
            int col = wn * 32 + nt * 8 + tig * 2;
            if (row < n)
                *(__half2*)&g_hh[(size_t)row * OC + col] = __floats2half2_rn(c[mt][nt][0], c[mt][nt][1]);
            if (row + 8 < n)
                *(__half2*)&g_hh[(size_t)(row + 8) * OC + col] = __floats2half2_rn(c[mt][nt][2], c[mt][nt][3]);
        }
    }
    int prow = row0 + pr;
    if (prow < n) {
        g_asrc[prow * HEADS + hp] = s_;
        g_adst[prow * HEADS + hp] = d_;
    }
}

// ---------------- CSR build ----------------
__global__ void k_count(const void* __restrict__ ei, int e) {
    int eidx = blockIdx.x * blockDim.x + threadIdx.x;
    if (eidx >= e) return;
    int dst = (g_idx64) ? (int)((const long long*)ei)[e + eidx]
                        : ((const int*)ei)[e + eidx];
    atomicAdd(&g_deg[dst], 1);
}

__global__ void k_scan(int n) {   // single block, 1024 threads; exclusive scan of g_deg -> g_off
    __shared__ int warpsum[32];
    int tid = threadIdx.x;
    int chunk = (n + 1023) / 1024;
    int beg = tid * chunk;
    int end = min(beg + chunk, n);
    int s = 0;
    for (int i = beg; i < end; i++) s += g_deg[i];
    int lane = tid & 31, wid = tid >> 5;
    int v = s;
#pragma unroll
    for (int o = 1; o < 32; o <<= 1) {
        int t = __shfl_up_sync(0xffffffffu, v, o);
        if (lane >= o) v += t;
    }
    if (lane == 31) warpsum[wid] = v;
    __syncthreads();
    if (wid == 0) {
        int w = warpsum[lane];
#pragma unroll
        for (int o = 1; o < 32; o <<= 1) {
            int t = __shfl_up_sync(0xffffffffu, w, o);
            if (lane >= o) w += t;
        }
        warpsum[lane] = w;
    }
    __syncthreads();
    int base = ((wid > 0) ? warpsum[wid - 1] : 0) + (v - s);
    int run = base;
    for (int i = beg; i < end; i++) { g_off[i] = run; run += g_deg[i]; }
    if (tid == 0) g_off[n] = warpsum[31];
}

__global__ void k_fill(const void* __restrict__ ei, int e) {
    int eidx = blockIdx.x * blockDim.x + threadIdx.x;
    if (eidx >= e) return;
    int2 sd = load_edge(ei, e, eidx);
    int pos = g_off[sd.y] + atomicAdd(&g_cur[sd.y], 1);
    g_csr_src[pos] = sd.x;
    g_csr_eid[pos] = eidx;
}

// ---------------- K agg: one warp per dst node; fp16 h gather; fused pooled ----------------
__global__ void k_agg(const float* __restrict__ bias, float* __restrict__ out,
                      float* __restrict__ pooled, int n) {
    int w = blockIdx.x * (blockDim.x >> 5) + (threadIdx.x >> 5);
    if (w >= n) return;
    int lane = threadIdx.x & 31;
    int hd = lane >> 3;

    int off = g_off[w];
    int deg = g_off[w + 1] - off;

    float ad = g_adst[w * HEADS + hd];
    float4 acc = make_float4(0.f, 0.f, 0.f, 0.f);
    float ssum = 0.f;

    int i = 0;
    for (; i + 3 < deg; i += 4) {
        int s0 = g_csr_src[off + i];
        int s1 = g_csr_src[off + i + 1];
        int s2 = g_csr_src[off + i + 2];
        int s3 = g_csr_src[off + i + 3];
        float ex0 = __expf(lrelu(g_asrc[s0 * HEADS + hd] + ad));
        float ex1 = __expf(lrelu(g_asrc[s1 * HEADS + hd] + ad));
        float ex2 = __expf(lrelu(g_asrc[s2 * HEADS + hd] + ad));
        float ex3 = __expf(lrelu(g_asrc[s3 * HEADS + hd] + ad));
        float4 v0 = ld_h4(&g_hh[(size_t)s0 * OC + lane * 4]);
        float4 v1 = ld_h4(&g_hh[(size_t)s1 * OC + lane * 4]);
        float4 v2 = ld_h4(&g_hh[(size_t)s2 * OC + lane * 4]);
        float4 v3 = ld_h4(&g_hh[(size_t)s3 * OC + lane * 4]);
        ssum += (ex0 + ex1) + (ex2 + ex3);
        acc.x = fmaf(ex0, v0.x, fmaf(ex1, v1.x, fmaf(ex2, v2.x, fmaf(ex3, v3.x, acc.x))));
        acc.y = fmaf(ex0, v0.y, fmaf(ex1, v1.y, fmaf(ex2, v2.y, fmaf(ex3, v3.y, acc.y))));
        acc.z = fmaf(ex0, v0.z, fmaf(ex1, v1.z, fmaf(ex2, v2.z, fmaf(ex3, v3.z, acc.z))));
        acc.w = fmaf(ex0, v0.w, fmaf(ex1, v1.w, fmaf(ex2, v2.w, fmaf(ex3, v3.w, acc.w))));
    }
    for (; i < deg; i++) {
        int s0 = g_csr_src[off + i];
        float ex0 = __expf(lrelu(g_asrc[s0 * HEADS + hd] + ad));
        float4 v0 = ld_h4(&g_hh[(size_t)s0 * OC + lane * 4]);
        ssum += ex0;
        acc.x = fmaf(ex0, v0.x, acc.x);
        acc.y = fmaf(ex0, v0.y, acc.y);
        acc.z = fmaf(ex0, v0.z, acc.z);
        acc.w = fmaf(ex0, v0.w, acc.w);
    }

    float inv = 1.f / (ssum + EPS_F);
    float4 b = *(const float4*)&bias[lane * 4];
    acc.x = fmaf(acc.x, inv, b.x);
    acc.y = fmaf(acc.y, inv, b.y);
    acc.z = fmaf(acc.z, inv, b.z);
    acc.w = fmaf(acc.w, inv, b.w);
    *(float4*)&out[(size_t)w * OC + lane * 4] = acc;

    // ---- fused pooled pass: lane-parallel over this node's edges ----
    float4 advec = *(const float4*)&g_adst[w * HEADS];
    float4 invvec;
    invvec.x = __shfl_sync(0xffffffffu, inv, 0);
    invvec.y = __shfl_sync(0xffffffffu, inv, 8);
    invvec.z = __shfl_sync(0xffffffffu, inv, 16);
    invvec.w = __shfl_sync(0xffffffffu, inv, 24);
    for (int j = lane; j < deg; j += 32) {
        int s   = g_csr_src[off + j];
        int eid = g_csr_eid[off + j];
        float4 as = *(const float4*)&g_asrc[s * HEADS];
        float p = __expf(lrelu(as.x + advec.x)) * invvec.x
                + __expf(lrelu(as.y + advec.y)) * invvec.y
                + __expf(lrelu(as.z + advec.z)) * invvec.z
                + __expf(lrelu(as.w + advec.w)) * invvec.w;
        pooled[eid] = p * 0.25f;
    }
}

// ---------------- launch ----------------
extern "C" void kernel_launch(void* const* d_in, const int* in_sizes, int n_in,
                              void* d_out, int out_size) {
    const float* x       = (const float*)d_in[0];
    const void*  ei      = d_in[1];
    const float* W       = (const float*)d_in[2];
    const float* att_src = (const float*)d_in[3];
    const float* att_dst = (const float*)d_in[4];
    const float* bias    = (const float*)d_in[5];

    int n = in_sizes[0] / IN_DIM;
    int e = in_sizes[1] / 2;

    float* out    = (float*)d_out;
    float* pooled = (float*)d_out + (size_t)n * OC;

    int smem = (2 * SM_XS + 2 * SM_WS + 8 * WAS_S) * sizeof(float);  // ~59.7 KB
    cudaFuncSetAttribute(k_gemm, cudaFuncAttributeMaxDynamicSharedMemorySize, smem);

    k_detect<<<1, 32>>>((const unsigned*)ei);
    k_zero<<<(n + 255) / 256, 256>>>(n);
    k_watt<<<4, 256>>>(W, att_src, att_dst);
    k_gemm<<<(n + TM - 1) / TM, 256, smem>>>(x, W, n);
    k_count<<<(e + 255) / 256, 256>>>(ei, e);
    k_scan<<<1, 1024>>>(n);
    k_fill<<<(e + 255) / 256, 256>>>(ei, e);
    k_agg<<<(n + 7) / 8, 256>>>(bias, out, pooled, n);
}